// round 4
// baseline (speedup 1.0000x reference)
#include <cuda_runtime.h>
#include <cstdint>

#define NU 100000
#define NI 50000
#define NE 1000000
#define EMB 64
#define DV 16   // float4 chunks per row

// ---------------------------------------------------------------------------
// __device__ scratch (no allocations allowed)
// ---------------------------------------------------------------------------
__device__ float g_u1[NU * EMB];     // round-1 user output
__device__ float g_i1[NI * EMB];     // round-1 item output
__device__ int   g_degU[NU];
__device__ int   g_degI[NI];
__device__ int   g_offU[NU + 1];
__device__ int   g_offI[NI + 1];
__device__ int   g_curU[NU];
__device__ int   g_curI[NI];
__device__ float g_invU[NU];
__device__ float g_invI[NI];
__device__ int   g_csrU[NE];         // per-user list of item neighbors
__device__ int   g_csrI[NE];         // per-item list of user neighbors

// ---------------------------------------------------------------------------
// Kernels
// ---------------------------------------------------------------------------
__global__ void zero_deg() {
    int i = blockIdx.x * blockDim.x + threadIdx.x;
    if (i < NU) g_degU[i] = 0;
    if (i < NI) g_degI[i] = 0;
}

__global__ void degree_kernel(const int* __restrict__ es, const int* __restrict__ ed) {
    int e = blockIdx.x * blockDim.x + threadIdx.x;
    if (e < NE) {
        atomicAdd(&g_degU[es[e]], 1);
        atomicAdd(&g_degI[ed[e]], 1);
    }
}

// Exclusive scan of degrees -> offsets (+cursors +inv_deg).
// Block 0: users (100k), Block 1: items (50k). 1024 threads each.
__global__ void scan_kernel() {
    __shared__ int ssum[1024];
    const int which = blockIdx.x;
    const int n     = which ? NI : NU;
    int*   deg = which ? g_degI : g_degU;
    int*   off = which ? g_offI : g_offU;
    int*   cur = which ? g_curI : g_curU;
    float* inv = which ? g_invI : g_invU;

    int t = threadIdx.x;
    int chunk = (n + 1023) >> 10;
    int lo = t * chunk;
    int hi = min(lo + chunk, n);

    int sum = 0;
    for (int i = lo; i < hi; i++) sum += deg[i];
    ssum[t] = sum;
    __syncthreads();

    // Hillis-Steele inclusive scan over 1024 thread sums
    for (int s = 1; s < 1024; s <<= 1) {
        int other = (t >= s) ? ssum[t - s] : 0;
        __syncthreads();
        ssum[t] += other;
        __syncthreads();
    }
    int prefix = ssum[t] - sum;   // exclusive prefix of this thread's chunk

    for (int i = lo; i < hi; i++) {
        int d = deg[i];
        off[i] = prefix;
        cur[i] = prefix;
        inv[i] = (d > 0) ? (1.0f / (float)d) : 0.0f;
        prefix += d;
    }
    if (t == 1023) off[n] = prefix;   // total edge count
}

__global__ void build_csr(const int* __restrict__ es, const int* __restrict__ ed) {
    int e = blockIdx.x * blockDim.x + threadIdx.x;
    if (e < NE) {
        int s = es[e], d = ed[e];
        g_csrI[atomicAdd(&g_curI[d], 1)] = s;   // item d's neighbor list: user s
        g_csrU[atomicAdd(&g_curU[s], 1)] = d;   // user s's neighbor list: item d
    }
}

// One fused round: pull-aggregate both directions + scale + residual.
// 16 threads per output row; lane c owns one float4 (16B chunk).
__global__ void __launch_bounds__(256)
round_kernel(const float4* __restrict__ uin,
             const float4* __restrict__ iin,
             const float*  __restrict__ usw,
             const float*  __restrict__ isw,
             float4* __restrict__ uout,
             float4* __restrict__ iout) {
    int t   = blockIdx.x * blockDim.x + threadIdx.x;
    int row = t >> 4;
    int c   = t & 15;

    const float4* src;
    const int*    adj;
    int off, end;
    float inv, sw;
    float4 x;
    float4* outp;
    int outIdx;

    if (row < NI) {
        // item row: gather user rows
        off = g_offI[row]; end = g_offI[row + 1];
        src = uin; adj = g_csrI;
        inv = g_invI[row]; sw = isw[row];
        outIdx = row * DV + c;
        x = iin[outIdx];
        outp = iout;
    } else if (row < NI + NU) {
        int u = row - NI;
        off = g_offU[u]; end = g_offU[u + 1];
        src = iin; adj = g_csrU;
        inv = g_invU[u]; sw = usw[u];
        outIdx = u * DV + c;
        x = uin[outIdx];
        outp = uout;
    } else {
        return;
    }

    float4 acc = make_float4(0.f, 0.f, 0.f, 0.f);
    int k = off;
    // unroll-4: 4 independent gathers in flight per lane
    for (; k + 4 <= end; k += 4) {
        int s0 = __ldg(&adj[k + 0]);
        int s1 = __ldg(&adj[k + 1]);
        int s2 = __ldg(&adj[k + 2]);
        int s3 = __ldg(&adj[k + 3]);
        float4 a = src[s0 * DV + c];
        float4 b = src[s1 * DV + c];
        float4 d = src[s2 * DV + c];
        float4 e = src[s3 * DV + c];
        acc.x += (a.x + b.x) + (d.x + e.x);
        acc.y += (a.y + b.y) + (d.y + e.y);
        acc.z += (a.z + b.z) + (d.z + e.z);
        acc.w += (a.w + b.w) + (d.w + e.w);
    }
    for (; k < end; k++) {
        float4 a = src[__ldg(&adj[k]) * DV + c];
        acc.x += a.x; acc.y += a.y; acc.z += a.z; acc.w += a.w;
    }

    float4 r;
    r.x = acc.x * inv + x.x * sw;
    r.y = acc.y * inv + x.y * sw;
    r.z = acc.z * inv + x.z * sw;
    r.w = acc.w * inv + x.w * sw;
    outp[outIdx] = r;
}

// ---------------------------------------------------------------------------
// Launch
// ---------------------------------------------------------------------------
extern "C" void kernel_launch(void* const* d_in, const int* in_sizes, int n_in,
                              void* d_out, int out_size) {
    const float* user_emb = (const float*)d_in[0];
    const float* item_emb = (const float*)d_in[1];
    const float* u_sw     = (const float*)d_in[2];
    const float* i_sw     = (const float*)d_in[3];
    const int*   e_src    = (const int*)d_in[4];
    const int*   e_dst    = (const int*)d_in[5];

    float* out_u = (float*)d_out;
    float* out_i = (float*)d_out + (int64_t)NU * EMB;

    void* p;
    cudaGetSymbolAddress(&p, g_u1); float4* u1p = (float4*)p;
    cudaGetSymbolAddress(&p, g_i1); float4* i1p = (float4*)p;

    const int TPB = 256;

    zero_deg<<<(NU + TPB - 1) / TPB, TPB>>>();
    degree_kernel<<<(NE + TPB - 1) / TPB, TPB>>>(e_src, e_dst);
    scan_kernel<<<2, 1024>>>();
    build_csr<<<(NE + TPB - 1) / TPB, TPB>>>(e_src, e_dst);

    int rows = NI + NU;
    int blocks = (rows * DV + TPB - 1) / TPB;

    // Round 1: in = original embeddings, out = u1/i1
    round_kernel<<<blocks, TPB>>>((const float4*)user_emb,
                                  (const float4*)item_emb,
                                  u_sw, i_sw,
                                  u1p, i1p);

    // Round 2: in = u1/i1, out = d_out
    round_kernel<<<blocks, TPB>>>((const float4*)u1p,
                                  (const float4*)i1p,
                                  u_sw, i_sw,
                                  (float4*)out_u, (float4*)out_i);
}